// round 13
// baseline (speedup 1.0000x reference)
#include <cuda_runtime.h>
#include <cstdint>

// CIRNet: T=2^20 rows x 18 feats. out = [r_predicts(N), regs(N), dts(N)], N=T-1.
// Persistent kernel, one wave (147 CTAs, 896 thr):
//   Phase A: TWO independent TMA pipelines per CTA. Warps 0-13 consume even
//            448-row tiles, warps 14-27 odd tiles; each group has its own
//            producer thread, 2 slots, full/empty mbarrier pairs. Empty
//            arrivals are warp-elected (count=14). No __syncthreads in loop.
//   Phase B: 2 sweeps (1 ODE + 1 Picard) affine scan via warp scan + block
//            scan + decoupled lookback (flags cleared at kernel entry).

#define FEAT      18
#define THREADS   896
#define NWARP     (THREADS / 32)          // 28
#define PER_TH    8
#define CHUNK     (THREADS * PER_TH)      // 7168 elements per block
#define TILE_ROWS 448
#define NTILES    (CHUNK / TILE_ROWS)     // 16
#define GTILES    (NTILES / 2)            // 8 tiles per group
#define GWARPS    14                      // warps per group
#define TILE_BYTES (TILE_ROWS * FEAT * 4) // 32256 bytes
#define MAXBLK    160
#define NSWEEP    2                        // sweep 0 = ODE, sweep 1 = Picard

__device__ volatile int   g_flag[NSWEEP][MAXBLK];   // 0 none, 1 aggregate, 2 inclusive
__device__ volatile float g_aggM[NSWEEP][MAXBLK];
__device__ volatile float g_aggB[NSWEEP][MAXBLK];
__device__ volatile float g_incR[NSWEEP][MAXBLK];   // block's outgoing state

__device__ __forceinline__ uint32_t smem_u32(const void* p) {
    return (uint32_t)__cvta_generic_to_shared(p);
}
__device__ __forceinline__ void mbar_init(uint32_t mbar, uint32_t cnt) {
    asm volatile("mbarrier.init.shared.b64 [%0], %1;" :: "r"(mbar), "r"(cnt) : "memory");
}
__device__ __forceinline__ void mbar_expect_tx(uint32_t mbar, uint32_t bytes) {
    asm volatile("mbarrier.arrive.expect_tx.shared.b64 _, [%0], %1;"
                 :: "r"(mbar), "r"(bytes) : "memory");
}
__device__ __forceinline__ void mbar_arrive_rel(uint32_t mbar) {
    asm volatile("mbarrier.arrive.release.cta.shared::cta.b64 _, [%0];"
                 :: "r"(mbar) : "memory");
}
__device__ __forceinline__ void mbar_wait(uint32_t mbar, uint32_t parity) {
    asm volatile(
        "{\n\t.reg .pred P;\n"
        "W%=:\n\t"
        "mbarrier.try_wait.parity.acquire.cta.shared::cta.b64 P, [%0], %1, 0x989680;\n\t"
        "@P bra D%=;\n\t"
        "bra W%=;\n"
        "D%=:\n\t}"
        :: "r"(mbar), "r"(parity) : "memory");
}
__device__ __forceinline__ void fence_proxy_async_cta() {
    asm volatile("fence.proxy.async.shared::cta;" ::: "memory");
}
__device__ __forceinline__ void tma_bulk_g2s(uint32_t dst_smem, const void* gsrc,
                                             uint32_t bytes, uint32_t mbar) {
    asm volatile(
        "cp.async.bulk.shared::cluster.global.mbarrier::complete_tx::bytes "
        "[%0], [%1], %2, [%3];"
        :: "r"(dst_smem), "l"(gsrc), "r"(bytes), "r"(mbar) : "memory");
}

extern "C" __global__ void __launch_bounds__(THREADS, 1)
cir_main(const float* __restrict__ trace,
         const float* __restrict__ sW, const float* __restrict__ sb,
         const float* __restrict__ eW,
         const float* __restrict__ kp, const float* __restrict__ thp,
         float* __restrict__ out, int N)
{
    extern __shared__ float sm[];
    float* s_bar  = sm;                           // 8 mbarriers: full[4], empty[4]
    float* s_bnd  = sm + 16;                      // [NTILES] boundary times
    float* s_dt   = s_bnd + NTILES;               // [CHUNK]
    float* s_p    = s_dt + CHUNK;                 // [CHUNK]
    float* s_stg  = s_p + CHUNK;                  // [4][TILE_ROWS*FEAT]
    float* s_wM   = s_stg + 4 * TILE_ROWS * FEAT; // [32]
    float* s_wB   = s_wM + 32;                    // [32]
    float* s_rin  = s_wB + 32;                    // [1]

    const int tid  = threadIdx.x;
    const int blk  = blockIdx.x;
    const int lane = tid & 31;
    const int warp = tid >> 5;

    const uint32_t barF = smem_u32(s_bar);        // full[s]  = barF + 8*s
    const uint32_t barE = barF + 32;              // empty[s] = barE + 8*s

    // clear this block's lookback flags (consumed >>10us later; single wave)
    if (tid < NSWEEP) g_flag[tid][blk] = 0;
    __threadfence();

    if (tid == 0) {
        #pragma unroll
        for (int s = 0; s < 4; s++) {
            mbar_init(barF + 8 * s, 1);
            mbar_init(barE + 8 * s, GWARPS);
        }
    }

    const float kk  = kp[0], th = thp[0];
    const float kth = kk * th;
    const float r0v = trace[1];                  // trace_data[0,1]
    const int rows_base = blk * CHUNK;

    const char* trc = reinterpret_cast<const char*>(trace);
    const long long tot_bytes = (long long)(N + 1) * FEAT * 4;

    // prefetch per-tile boundary times (time of first row of next tile)
    if (tid < NTILES) {
        long long idx = (long long)(rows_base + (tid + 1) * TILE_ROWS);
        s_bnd[tid] = (idx <= (long long)N) ? trace[idx * FEAT] : 0.0f;
    }
    __syncthreads();     // barriers + s_bnd visible to all

    const int grp  = (tid >= 448) ? 1 : 0;       // consumer group
    const int gtid = tid - grp * 448;            // 0..447 within group

    // issue group-local tile q for group g (single thread per group)
    auto issue = [&](int g, int q) {
        int tl   = 2 * q + g;                    // global tile
        int slot = g * 2 + (q & 1);
        long long start = (long long)(rows_base + tl * TILE_ROWS) * FEAT * 4;
        long long avail = tot_bytes - start;
        uint32_t sz = (avail <= 0) ? 0u :
                      (avail < TILE_BYTES ? (uint32_t)avail : (uint32_t)TILE_BYTES);
        uint32_t mb = barF + 8 * slot;
        mbar_expect_tx(mb, sz);
        if (sz) tma_bulk_g2s(smem_u32(s_stg + slot * TILE_ROWS * FEAT),
                             trc + start, sz, mb);
    };
    if (gtid == 0) { fence_proxy_async_cta(); issue(grp, 0); issue(grp, 1); }

    float wS[8], wE[8];
    #pragma unroll
    for (int q = 0; q < 8; q++) { wS[q] = sW[q]; wE[q] = eW[q]; }
    const float sbv = sb[0];

    // ------------- Phase A: two decoupled producer/consumer streams --------
    for (int q = 0; q < GTILES; q++) {
        const int tl   = 2 * q + grp;
        const int slot = grp * 2 + (q & 1);
        const uint32_t par = (q >> 1) & 1;
        mbar_wait(barF + 8 * slot, par);          // acquire tile data

        float* buf = s_stg + slot * TILE_ROWS * FEAT;
        const int r = gtid;                       // row within tile
        const int i = rows_base + tl * TILE_ROWS + r;
        float dt = 0.0f, p = 0.0f;
        if (i < N) {
            const float2* row2 = reinterpret_cast<const float2*>(buf + r * FEAT);
            float tc = row2[0].x;
            float tn = (r < TILE_ROWS - 1) ? buf[(r + 1) * FEAT] : s_bnd[tl];
            dt = tn - tc;
            float sig = sbv, eps = 0.0f;
            #pragma unroll
            for (int qq = 0; qq < 4; qq++) {
                float2 f = row2[1 + qq];
                sig = fmaf(f.x, wS[2 * qq], sig);
                sig = fmaf(f.y, wS[2 * qq + 1], sig);
            }
            #pragma unroll
            for (int qq = 0; qq < 4; qq++) {
                float2 f = row2[5 + qq];
                eps = fmaf(f.x, wE[2 * qq], eps);
                eps = fmaf(f.y, wE[2 * qq + 1], eps);
            }
            p = sig * eps;
            __stcs(&out[N + i],     fmaf(2.0f * kk, th, -sig * sig));  // regs
            __stcs(&out[2 * N + i], dt);                               // dts
        }
        s_dt[tl * TILE_ROWS + r] = dt;
        s_p [tl * TILE_ROWS + r] = p;

        // warp-elected release of the slot (reads already consumed into regs)
        __syncwarp();
        if (lane == 0) mbar_arrive_rel(barE + 8 * slot);

        // group producer: refill this slot with group-tile q+2
        if (gtid == 0 && q + 2 < GTILES) {
            mbar_wait(barE + 8 * slot, par);
            fence_proxy_async_cta();
            issue(grp, q + 2);
        }
    }

    __syncthreads();     // join groups; s_dt/s_p fully visible

    // Per-thread contiguous segment -> registers (persist across all sweeps)
    const int eb = tid * PER_TH;
    float ldt[PER_TH], lp[PER_TH], lb[PER_TH];
    #pragma unroll
    for (int u = 0; u < PER_TH; u++) {
        ldt[u] = s_dt[eb + u];
        lp[u]  = s_p[eb + u];
        lb[u]  = kth * ldt[u];       // sweep-0 (ODE) b-coefficient
    }

    // --------------------------- Phase B: sweeps ---------------------------
    for (int j = 0; j < NSWEEP; j++) {
        const bool last = (j == NSWEEP - 1);

        // local affine compose over the thread's PER_TH steps
        float M = 1.0f, B = 0.0f;
        #pragma unroll
        for (int u = 0; u < PER_TH; u++) {
            float m = fmaf(-kk, ldt[u], 1.0f);
            B = fmaf(m, B, lb[u]);
            M *= m;
        }

        // warp inclusive scan of transforms (lower lane applied first)
        float iM = M, iB = B;
        #pragma unroll
        for (int off = 1; off < 32; off <<= 1) {
            float pm = __shfl_up_sync(0xFFFFFFFFu, iM, off);
            float pb = __shfl_up_sync(0xFFFFFFFFu, iB, off);
            if (lane >= off) { iB = fmaf(iM, pb, iB); iM *= pm; }
        }
        float eM = __shfl_up_sync(0xFFFFFFFFu, iM, 1);
        float eB = __shfl_up_sync(0xFFFFFFFFu, iB, 1);
        if (lane == 0) { eM = 1.0f; eB = 0.0f; }
        if (lane == 31) { s_wM[warp] = iM; s_wB[warp] = iB; }
        __syncthreads();

        if (warp == 0) {
            // scan the NWARP warp aggregates (pad to 32 with identity)
            float jM = (lane < NWARP) ? s_wM[lane] : 1.0f;
            float jB = (lane < NWARP) ? s_wB[lane] : 0.0f;
            #pragma unroll
            for (int off = 1; off < 32; off <<= 1) {
                float pm = __shfl_up_sync(0xFFFFFFFFu, jM, off);
                float pb = __shfl_up_sync(0xFFFFFFFFu, jB, off);
                if (lane >= off) { jB = fmaf(jM, pb, jB); jM *= pm; }
            }
            float xM = __shfl_up_sync(0xFFFFFFFFu, jM, 1);
            float xB = __shfl_up_sync(0xFFFFFFFFu, jB, 1);
            if (lane == 0) { xM = 1.0f; xB = 0.0f; }
            if (lane < NWARP) { s_wM[lane] = xM; s_wB[lane] = xB; }
            float Mblk = __shfl_sync(0xFFFFFFFFu, jM, 31);
            float Bblk = __shfl_sync(0xFFFFFFFFu, jB, 31);

            // decoupled lookback -> incoming state r_in for this block
            float rin;
            if (blk == 0) {
                rin = r0v;
            } else {
                if (lane == 0) {
                    g_aggM[j][blk] = Mblk; g_aggB[j][blk] = Bblk;
                    __threadfence();
                    g_flag[j][blk] = 1;
                }
                float Mc = 1.0f, Bc = 0.0f;   // maps r_in(idx+1) -> r_in(blk)
                int idx = blk - 1;
                for (;;) {
                    int jj = idx - lane;
                    int fl = 1; float Mv = 1.0f, Bv = 0.0f;
                    if (jj >= 0) {
                        do { fl = g_flag[j][jj]; } while (fl == 0);
                        __threadfence();
                        if (fl == 2) { Mv = 0.0f; Bv = g_incR[j][jj]; }
                        else         { Mv = g_aggM[j][jj]; Bv = g_aggB[j][jj]; }
                    }
                    unsigned bal = __ballot_sync(0xFFFFFFFFu, (jj >= 0) && (fl == 2));
                    if (bal) {
                        int ls = __ffs(bal) - 1;     // nearest inclusive block
                        if (lane > ls) { Mv = 1.0f; Bv = 0.0f; }
                    }
                    // ordered reduction (lane0 outermost)
                    #pragma unroll
                    for (int off = 1; off < 32; off <<= 1) {
                        float Mo = __shfl_down_sync(0xFFFFFFFFu, Mv, off);
                        float Bo = __shfl_down_sync(0xFFFFFFFFu, Bv, off);
                        if (lane + off < 32) { Bv = fmaf(Mv, Bo, Bv); Mv *= Mo; }
                    }
                    if (lane == 0) { Bc = fmaf(Mc, Bv, Bc); Mc *= Mv; }
                    if (bal) break;
                    idx -= 32;
                }
                rin = __shfl_sync(0xFFFFFFFFu, Bc, 0);
            }
            if (lane == 0) {
                g_incR[j][blk] = fmaf(Mblk, rin, Bblk);
                __threadfence();
                g_flag[j][blk] = 2;
                *s_rin = rin;
            }
        }
        __syncthreads();

        // seed this thread's state and replay its steps
        const float rin = *s_rin;
        const float wm = s_wM[warp], wb = s_wB[warp];
        float r = fmaf(eM * wm, rin, fmaf(eM, wb, eB));

        if (last) {
            float ro[PER_TH];
            #pragma unroll
            for (int u = 0; u < PER_TH; u++) {
                float m = fmaf(-kk, ldt[u], 1.0f);
                r = fmaf(m, r, lb[u]);
                ro[u] = r;                         // r_predicts[i] = r_{i+1}
            }
            const int gi = rows_base + eb;
            if (gi + PER_TH <= N) {
                float4* o4 = reinterpret_cast<float4*>(out + gi);
                __stcs(&o4[0], make_float4(ro[0], ro[1], ro[2], ro[3]));
                __stcs(&o4[1], make_float4(ro[4], ro[5], ro[6], ro[7]));
            } else {
                for (int u = 0; u < PER_TH; u++)
                    if (gi + u < N) out[gi + u] = ro[u];
            }
        } else {
            #pragma unroll
            for (int u = 0; u < PER_TH; u++) {
                float m  = fmaf(-kk, ldt[u], 1.0f);
                float bc = lb[u];
                // next sweep's b uses r^{(j)}_i = current r (state entering step i)
                lb[u] = fmaf(lp[u], sqrtf(fabsf(r * ldt[u])), kth * ldt[u]);
                r = fmaf(m, r, bc);
            }
        }
        __syncthreads();   // protect s_wM/s_rin reuse by the next sweep
    }
}

// ---------------------------------------------------------------------------
extern "C" void kernel_launch(void* const* d_in, const int* in_sizes, int n_in,
                              void* d_out, int out_size)
{
    const float* trace = (const float*)d_in[0];
    const float* sW    = (const float*)d_in[1];
    const float* sb    = (const float*)d_in[2];
    const float* eW    = (const float*)d_in[3];
    const float* kp    = (const float*)d_in[4];
    const float* thp   = (const float*)d_in[5];
    float* out = (float*)d_out;

    int N    = out_size / 3;                       // 1048575
    int nblk = (N + CHUNK - 1) / CHUNK;            // 147 (one wave, 1 CTA/SM)

    size_t shbytes = (size_t)(16 + NTILES + 2 * CHUNK + 4 * TILE_ROWS * FEAT + 72)
                     * sizeof(float);
    cudaFuncSetAttribute(cir_main, cudaFuncAttributeMaxDynamicSharedMemorySize,
                         (int)shbytes);

    cir_main<<<nblk, THREADS, shbytes>>>(trace, sW, sb, eW, kp, thp, out, N);
}

// round 15
// speedup vs baseline: 1.0464x; 1.0464x over previous
#include <cuda_runtime.h>
#include <cstdint>

// CIRNet: T=2^20 rows x 18 feats. out = [r_predicts(N), regs(N), dts(N)], N=T-1.
// Persistent kernel, one wave (147 CTAs, 512 thr, PER_TH=14):
//   Phase A: 4-slot TMA ring over 512-row tiles. Producer issues 4 tiles
//            upfront; steady state keeps 3 tiles (~110KB) in flight per SM.
//            Warp-elected empty arrivals; no __syncthreads in the loop.
//            (R14 fix: s_bnd padded to 16 floats so s_stg is 16B-aligned --
//             cp.async.bulk traps on misaligned smem destination.)
//   Phase B: 2 sweeps (1 ODE + 1 Picard) affine scan via warp scan + block
//            scan + decoupled lookback (flags cleared at kernel entry).

#define FEAT      18
#define THREADS   512
#define NWARP     (THREADS / 32)          // 16
#define PER_TH    14
#define CHUNK     (THREADS * PER_TH)      // 7168 elements per block
#define TILE_ROWS 512
#define NTILES    (CHUNK / TILE_ROWS)     // 14
#define BND_PAD   16                      // s_bnd padded for 16B alignment of s_stg
#define NSLOT     4
#define TILE_BYTES (TILE_ROWS * FEAT * 4) // 36864 bytes (16B multiple)
#define MAXBLK    160
#define NSWEEP    2                        // sweep 0 = ODE, sweep 1 = Picard

__device__ volatile int   g_flag[NSWEEP][MAXBLK];   // 0 none, 1 aggregate, 2 inclusive
__device__ volatile float g_aggM[NSWEEP][MAXBLK];
__device__ volatile float g_aggB[NSWEEP][MAXBLK];
__device__ volatile float g_incR[NSWEEP][MAXBLK];   // block's outgoing state

__device__ __forceinline__ uint32_t smem_u32(const void* p) {
    return (uint32_t)__cvta_generic_to_shared(p);
}
__device__ __forceinline__ void mbar_init(uint32_t mbar, uint32_t cnt) {
    asm volatile("mbarrier.init.shared.b64 [%0], %1;" :: "r"(mbar), "r"(cnt) : "memory");
}
__device__ __forceinline__ void mbar_expect_tx(uint32_t mbar, uint32_t bytes) {
    asm volatile("mbarrier.arrive.expect_tx.shared.b64 _, [%0], %1;"
                 :: "r"(mbar), "r"(bytes) : "memory");
}
__device__ __forceinline__ void mbar_arrive_rel(uint32_t mbar) {
    asm volatile("mbarrier.arrive.release.cta.shared::cta.b64 _, [%0];"
                 :: "r"(mbar) : "memory");
}
__device__ __forceinline__ void mbar_wait(uint32_t mbar, uint32_t parity) {
    asm volatile(
        "{\n\t.reg .pred P;\n"
        "W%=:\n\t"
        "mbarrier.try_wait.parity.acquire.cta.shared::cta.b64 P, [%0], %1, 0x989680;\n\t"
        "@P bra D%=;\n\t"
        "bra W%=;\n"
        "D%=:\n\t}"
        :: "r"(mbar), "r"(parity) : "memory");
}
__device__ __forceinline__ void fence_proxy_async_cta() {
    asm volatile("fence.proxy.async.shared::cta;" ::: "memory");
}
__device__ __forceinline__ void tma_bulk_g2s(uint32_t dst_smem, const void* gsrc,
                                             uint32_t bytes, uint32_t mbar) {
    asm volatile(
        "cp.async.bulk.shared::cluster.global.mbarrier::complete_tx::bytes "
        "[%0], [%1], %2, [%3];"
        :: "r"(dst_smem), "l"(gsrc), "r"(bytes), "r"(mbar) : "memory");
}

extern "C" __global__ void __launch_bounds__(THREADS, 1)
cir_main(const float* __restrict__ trace,
         const float* __restrict__ sW, const float* __restrict__ sb,
         const float* __restrict__ eW,
         const float* __restrict__ kp, const float* __restrict__ thp,
         float* __restrict__ out, int N)
{
    extern __shared__ float sm[];
    float* s_bar  = sm;                           // 8 mbarriers (64B)
    float* s_bnd  = sm + 16;                      // [BND_PAD] boundary times
    float* s_dt   = s_bnd + BND_PAD;              // [CHUNK] (reused as out-stage)
    float* s_p    = s_dt + CHUNK;                 // [CHUNK]
    float* s_stg  = s_p + CHUNK;                  // [NSLOT][TILE_ROWS*FEAT] 16B-aligned
    float* s_wM   = s_stg + NSLOT * TILE_ROWS * FEAT;  // [32]
    float* s_wB   = s_wM + 32;                    // [32]
    float* s_rin  = s_wB + 32;                    // [1]

    const int tid  = threadIdx.x;
    const int blk  = blockIdx.x;
    const int lane = tid & 31;
    const int warp = tid >> 5;

    const uint32_t barF = smem_u32(s_bar);        // full[s]  = barF + 8*s
    const uint32_t barE = barF + 32;              // empty[s] = barE + 8*s

    // clear this block's lookback flags (consumed >>10us later; single wave)
    if (tid < NSWEEP) g_flag[tid][blk] = 0;
    __threadfence();

    if (tid == 0) {
        #pragma unroll
        for (int s = 0; s < NSLOT; s++) {
            mbar_init(barF + 8 * s, 1);
            mbar_init(barE + 8 * s, NWARP);
        }
    }

    const float kk  = kp[0], th = thp[0];
    const float kth = kk * th;
    const float r0v = trace[1];                  // trace_data[0,1]
    const int rows_base = blk * CHUNK;

    const char* trc = reinterpret_cast<const char*>(trace);
    const long long tot_bytes = (long long)(N + 1) * FEAT * 4;

    // prefetch per-tile boundary times (time of first row of next tile)
    if (tid < NTILES) {
        long long idx = (long long)(rows_base + (tid + 1) * TILE_ROWS);
        s_bnd[tid] = (idx <= (long long)N) ? trace[idx * FEAT] : 0.0f;
    }
    __syncthreads();     // barriers + s_bnd visible to all

    // issue tile t into slot t%NSLOT (thread 0 only)
    auto issue = [&](int t) {
        int slot = t & (NSLOT - 1);
        long long start = (long long)(rows_base + t * TILE_ROWS) * FEAT * 4;
        long long avail = tot_bytes - start;
        uint32_t sz = (avail <= 0) ? 0u :
                      (avail < TILE_BYTES ? (uint32_t)avail : (uint32_t)TILE_BYTES);
        sz &= ~15u;      // keep bulk size 16B multiple (tail rounds down; the
                         // dropped <16B belong to row N's tail, never read)
        uint32_t mb = barF + 8 * slot;
        mbar_expect_tx(mb, sz);
        if (sz) tma_bulk_g2s(smem_u32(s_stg + slot * TILE_ROWS * FEAT),
                             trc + start, sz, mb);
    };
    if (tid == 0) {
        fence_proxy_async_cta();
        issue(0); issue(1); issue(2); issue(3);   // 4 tiles upfront
    }

    float wS[8], wE[8];
    #pragma unroll
    for (int q = 0; q < 8; q++) { wS[q] = sW[q]; wE[q] = eW[q]; }
    const float sbv = sb[0];

    // ------------- Phase A: deep-pipelined producer/consumer loop ----------
    for (int tl = 0; tl < NTILES; tl++) {
        const int slot = tl & (NSLOT - 1);
        const uint32_t par = (tl / NSLOT) & 1;
        mbar_wait(barF + 8 * slot, par);          // acquire tile data

        float* buf = s_stg + slot * TILE_ROWS * FEAT;
        const int r = tid;                        // row within tile
        const int i = rows_base + tl * TILE_ROWS + r;
        float dt = 0.0f, p = 0.0f;
        if (i < N) {
            const float2* row2 = reinterpret_cast<const float2*>(buf + r * FEAT);
            float tc = row2[0].x;
            float tn = (r < TILE_ROWS - 1) ? buf[(r + 1) * FEAT] : s_bnd[tl];
            dt = tn - tc;
            float sig = sbv, eps = 0.0f;
            #pragma unroll
            for (int qq = 0; qq < 4; qq++) {
                float2 f = row2[1 + qq];
                sig = fmaf(f.x, wS[2 * qq], sig);
                sig = fmaf(f.y, wS[2 * qq + 1], sig);
            }
            #pragma unroll
            for (int qq = 0; qq < 4; qq++) {
                float2 f = row2[5 + qq];
                eps = fmaf(f.x, wE[2 * qq], eps);
                eps = fmaf(f.y, wE[2 * qq + 1], eps);
            }
            p = sig * eps;
            __stcs(&out[N + i],     fmaf(2.0f * kk, th, -sig * sig));  // regs
            __stcs(&out[2 * N + i], dt);                               // dts
        }
        s_dt[tl * TILE_ROWS + r] = dt;
        s_p [tl * TILE_ROWS + r] = p;

        // warp-elected release of the slot
        __syncwarp();
        if (lane == 0) mbar_arrive_rel(barE + 8 * slot);

        // producer: refill this slot with tile tl+NSLOT once all warps released
        if (tid == 0 && tl + NSLOT < NTILES) {
            mbar_wait(barE + 8 * slot, par);
            fence_proxy_async_cta();
            issue(tl + NSLOT);
        }
    }

    __syncthreads();     // join warps; s_dt/s_p fully visible

    // Per-thread contiguous segment -> registers (persist across all sweeps)
    const int eb = tid * PER_TH;
    float ldt[PER_TH], lp[PER_TH], lb[PER_TH];
    #pragma unroll
    for (int u = 0; u < PER_TH; u++) {
        ldt[u] = s_dt[eb + u];
        lp[u]  = s_p[eb + u];
        lb[u]  = kth * ldt[u];       // sweep-0 (ODE) b-coefficient
    }

    // --------------------------- Phase B: sweeps ---------------------------
    for (int j = 0; j < NSWEEP; j++) {
        const bool last = (j == NSWEEP - 1);

        // local affine compose over the thread's PER_TH steps
        float M = 1.0f, B = 0.0f;
        #pragma unroll
        for (int u = 0; u < PER_TH; u++) {
            float m = fmaf(-kk, ldt[u], 1.0f);
            B = fmaf(m, B, lb[u]);
            M *= m;
        }

        // warp inclusive scan of transforms (lower lane applied first)
        float iM = M, iB = B;
        #pragma unroll
        for (int off = 1; off < 32; off <<= 1) {
            float pm = __shfl_up_sync(0xFFFFFFFFu, iM, off);
            float pb = __shfl_up_sync(0xFFFFFFFFu, iB, off);
            if (lane >= off) { iB = fmaf(iM, pb, iB); iM *= pm; }
        }
        float eM = __shfl_up_sync(0xFFFFFFFFu, iM, 1);
        float eB = __shfl_up_sync(0xFFFFFFFFu, iB, 1);
        if (lane == 0) { eM = 1.0f; eB = 0.0f; }
        if (lane == 31) { s_wM[warp] = iM; s_wB[warp] = iB; }
        __syncthreads();

        if (warp == 0) {
            // scan the NWARP warp aggregates (pad to 32 with identity)
            float jM = (lane < NWARP) ? s_wM[lane] : 1.0f;
            float jB = (lane < NWARP) ? s_wB[lane] : 0.0f;
            #pragma unroll
            for (int off = 1; off < 32; off <<= 1) {
                float pm = __shfl_up_sync(0xFFFFFFFFu, jM, off);
                float pb = __shfl_up_sync(0xFFFFFFFFu, jB, off);
                if (lane >= off) { jB = fmaf(jM, pb, jB); jM *= pm; }
            }
            float xM = __shfl_up_sync(0xFFFFFFFFu, jM, 1);
            float xB = __shfl_up_sync(0xFFFFFFFFu, jB, 1);
            if (lane == 0) { xM = 1.0f; xB = 0.0f; }
            if (lane < NWARP) { s_wM[lane] = xM; s_wB[lane] = xB; }
            float Mblk = __shfl_sync(0xFFFFFFFFu, jM, 31);
            float Bblk = __shfl_sync(0xFFFFFFFFu, jB, 31);

            // decoupled lookback -> incoming state r_in for this block
            float rin;
            if (blk == 0) {
                rin = r0v;
            } else {
                if (lane == 0) {
                    g_aggM[j][blk] = Mblk; g_aggB[j][blk] = Bblk;
                    __threadfence();
                    g_flag[j][blk] = 1;
                }
                float Mc = 1.0f, Bc = 0.0f;   // maps r_in(idx+1) -> r_in(blk)
                int idx = blk - 1;
                for (;;) {
                    int jj = idx - lane;
                    int fl = 1; float Mv = 1.0f, Bv = 0.0f;
                    if (jj >= 0) {
                        do { fl = g_flag[j][jj]; } while (fl == 0);
                        __threadfence();
                        if (fl == 2) { Mv = 0.0f; Bv = g_incR[j][jj]; }
                        else         { Mv = g_aggM[j][jj]; Bv = g_aggB[j][jj]; }
                    }
                    unsigned bal = __ballot_sync(0xFFFFFFFFu, (jj >= 0) && (fl == 2));
                    if (bal) {
                        int ls = __ffs(bal) - 1;     // nearest inclusive block
                        if (lane > ls) { Mv = 1.0f; Bv = 0.0f; }
                    }
                    // ordered reduction (lane0 outermost)
                    #pragma unroll
                    for (int off = 1; off < 32; off <<= 1) {
                        float Mo = __shfl_down_sync(0xFFFFFFFFu, Mv, off);
                        float Bo = __shfl_down_sync(0xFFFFFFFFu, Bv, off);
                        if (lane + off < 32) { Bv = fmaf(Mv, Bo, Bv); Mv *= Mo; }
                    }
                    if (lane == 0) { Bc = fmaf(Mc, Bv, Bc); Mc *= Mv; }
                    if (bal) break;
                    idx -= 32;
                }
                rin = __shfl_sync(0xFFFFFFFFu, Bc, 0);
            }
            if (lane == 0) {
                g_incR[j][blk] = fmaf(Mblk, rin, Bblk);
                __threadfence();
                g_flag[j][blk] = 2;
                *s_rin = rin;
            }
        }
        __syncthreads();

        // seed this thread's state and replay its steps
        const float rin = *s_rin;
        const float wm = s_wM[warp], wb = s_wB[warp];
        float r = fmaf(eM * wm, rin, fmaf(eM, wb, eB));

        if (last) {
            // replay + stage output into s_dt (dead after register load),
            // then coalesced streaming stores
            #pragma unroll
            for (int u = 0; u < PER_TH; u++) {
                float m = fmaf(-kk, ldt[u], 1.0f);
                r = fmaf(m, r, lb[u]);
                s_dt[eb + u] = r;                  // r_predicts[i] = r_{i+1}
            }
            __syncthreads();
            #pragma unroll
            for (int q = 0; q < PER_TH; q++) {
                int k  = q * THREADS + tid;
                int gi = rows_base + k;
                if (gi < N) __stcs(&out[gi], s_dt[k]);
            }
        } else {
            #pragma unroll
            for (int u = 0; u < PER_TH; u++) {
                float m  = fmaf(-kk, ldt[u], 1.0f);
                float bc = lb[u];
                // next sweep's b uses r^{(j)}_i = current r (state entering step i)
                lb[u] = fmaf(lp[u], sqrtf(fabsf(r * ldt[u])), kth * ldt[u]);
                r = fmaf(m, r, bc);
            }
            __syncthreads();   // protect s_wM/s_rin reuse by the next sweep
        }
    }
}

// ---------------------------------------------------------------------------
extern "C" void kernel_launch(void* const* d_in, const int* in_sizes, int n_in,
                              void* d_out, int out_size)
{
    const float* trace = (const float*)d_in[0];
    const float* sW    = (const float*)d_in[1];
    const float* sb    = (const float*)d_in[2];
    const float* eW    = (const float*)d_in[3];
    const float* kp    = (const float*)d_in[4];
    const float* thp   = (const float*)d_in[5];
    float* out = (float*)d_out;

    int N    = out_size / 3;                       // 1048575
    int nblk = (N + CHUNK - 1) / CHUNK;            // 147 (one wave, 1 CTA/SM)

    size_t shbytes = (size_t)(16 + BND_PAD + 2 * CHUNK + NSLOT * TILE_ROWS * FEAT + 72)
                     * sizeof(float);
    cudaFuncSetAttribute(cir_main, cudaFuncAttributeMaxDynamicSharedMemorySize,
                         (int)shbytes);

    cir_main<<<nblk, THREADS, shbytes>>>(trace, sW, sb, eW, kp, thp, out, N);
}